// round 5
// baseline (speedup 1.0000x reference)
#include <cuda_runtime.h>
#include <cuda_bf16.h>
#include <cstdint>

// ---------------- problem constants ----------------
#define N_IN   200000
#define N_OUT  100000
#define NE     1600000
#define CIN    64
#define CO     128
#define KHALF  576
#define MTILE  128
#define MPAD   100096          // 782 * 128
#define NTILES 782
#define KCH    16              // K elems per pipeline chunk
#define NCHUNK 36              // 576 / 16
#define SLOT   24576           // 6 arrays x [128][16] bf16 (4KB each)

#define ASZ    ((size_t)MPAD * KHALF)
#define BSZ    ((size_t)CO * KHALF)

// ---------------- device scratch (no allocs allowed) ----------------
__device__ int            g_offs[N_OUT + 1];
__device__ float          g_imp[N_OUT];
// A arrays: 0=Auh 1=Aul 2=Awh 3=Awl ; padded rows stay zero (.bss)
__device__ __nv_bfloat16  g_A[4][ASZ];
// B arrays: 0=Bh 1=Bl
__device__ __nv_bfloat16  g_B[2][BSZ];

// ---------------- helpers ----------------
__device__ __forceinline__ uint32_t smem_u32(const void* p) {
    uint32_t a;
    asm("{ .reg .u64 t; cvta.to.shared.u64 t, %1; cvt.u32.u64 %0, t; }"
        : "=r"(a) : "l"(p));
    return a;
}
// 16B-granule swizzle for 32B rows: bits[4:6] ^= row低bits -> conflict-free ldmatrix
__device__ __forceinline__ uint32_t sw32(uint32_t o) {
    return o ^ ((o >> 1) & 0x70);
}
__device__ __forceinline__ void cp16(uint32_t dst, const void* src) {
    asm volatile("cp.async.cg.shared.global [%0], [%1], 16;" :: "r"(dst), "l"(src));
}
#define CP_COMMIT asm volatile("cp.async.commit_group;" ::: "memory")

__device__ __forceinline__ void ldm4(uint32_t& r0, uint32_t& r1,
                                     uint32_t& r2, uint32_t& r3, uint32_t a) {
    asm volatile("ldmatrix.sync.aligned.m8n8.x4.shared.b16 {%0,%1,%2,%3}, [%4];"
                 : "=r"(r0), "=r"(r1), "=r"(r2), "=r"(r3) : "r"(a));
}
__device__ __forceinline__ void mma_bf16(float* c, const uint32_t* a,
                                         uint32_t b0, uint32_t b1) {
    asm volatile(
        "mma.sync.aligned.m16n8k16.row.col.f32.bf16.bf16.f32 "
        "{%0,%1,%2,%3}, {%4,%5,%6,%7}, {%8,%9}, {%0,%1,%2,%3};"
        : "+f"(c[0]), "+f"(c[1]), "+f"(c[2]), "+f"(c[3])
        : "r"(a[0]), "r"(a[1]), "r"(a[2]), "r"(a[3]), "r"(b0), "r"(b1));
}

// ---------------------------------------------------------------------------
// Kernel 1: CSR offsets via adjacent-diff over sorted neighbors_out_index
// ---------------------------------------------------------------------------
__global__ void build_offsets_kernel(const int* __restrict__ out_idx) {
    int e = blockIdx.x * blockDim.x + threadIdx.x;
    if (e >= NE) return;
    int b = __ldg(out_idx + e);
    int a = (e == 0) ? -1 : __ldg(out_idx + e - 1);
    for (int n = a + 1; n <= b; n++) g_offs[n] = e;
    if (e == NE - 1)
        for (int n = b + 1; n <= N_OUT; n++) g_offs[n] = NE;
}

// ---------------------------------------------------------------------------
// Kernel 2: compressed weights [128][576] bf16 hi/lo
// ---------------------------------------------------------------------------
__global__ void build_w_kernel(const float* __restrict__ Wa,
                               const float* __restrict__ Wb) {
    int i = blockIdx.x * blockDim.x + threadIdx.x;
    if (i >= CO * KHALF) return;
    int o = i / KHALF, k = i % KHALF;
    float v = (o < 96) ? __ldg(Wa + k * 96 + o) : __ldg(Wb + k * 32 + (o - 96));
    __nv_bfloat16 h = __float2bfloat16(v);
    g_B[0][i] = h;
    g_B[1][i] = __float2bfloat16(v - __bfloat162float(h));
}

// ---------------------------------------------------------------------------
// Kernel 3: binning. One warp per point; bins live in REGISTERS (lane owns
// channels 2l,2l+1). Edges grabbed 32 at a time; ballot+shfl serialize edges
// of each kernel element so the accumulator index is compile-time.
// ---------------------------------------------------------------------------
__global__ __launch_bounds__(256)
void bin_kernel(const float* __restrict__ feats,
                const float* __restrict__ importance,
                const int*   __restrict__ nbr,
                const int*   __restrict__ kid,
                float*       __restrict__ out) {
    const int lane = threadIdx.x & 31;
    const int n    = blockIdx.x * 8 + (threadIdx.x >> 5);

    float2 u[9], w[9];
    #pragma unroll
    for (int k = 0; k < 9; k++) {
        u[k] = make_float2(0.f, 0.f);
        w[k] = make_float2(0.f, 0.f);
    }
    float impacc = 0.f;

    const int e0 = g_offs[n], e1 = g_offs[n + 1];
    for (int base = e0; base < e1; base += 32) {
        const int  e     = base + lane;
        const bool valid = e < e1;
        const int  src   = valid ? __ldg(nbr + e) : 0;
        const int  k     = valid ? __ldg(kid + e) : -1;
        const float im   = valid ? __ldg(importance + src) : 0.f;
        impacc += im;
        #pragma unroll
        for (int kk = 0; kk < 9; kk++) {
            unsigned m = __ballot_sync(0xffffffffu, k == kk);
            while (m) {
                const int s = __ffs(m) - 1;
                m &= m - 1;
                const int   ssrc = __shfl_sync(0xffffffffu, src, s);
                const float sim  = __shfl_sync(0xffffffffu, im, s);
                const float2 f = *reinterpret_cast<const float2*>(
                                     feats + (size_t)ssrc * CIN + 2 * lane);
                u[kk].x += f.x;
                u[kk].y += f.y;
                w[kk].x = fmaf(f.x, sim, w[kk].x);
                w[kk].y = fmaf(f.y, sim, w[kk].y);
            }
        }
    }

    // warp-sum of importance
    #pragma unroll
    for (int s = 16; s > 0; s >>= 1)
        impacc += __shfl_xor_sync(0xffffffffu, impacc, s);

    // writeout: hi/lo bf16 split, bf16x2 per lane per (k, array)
    const size_t rb = (size_t)n * KHALF;
    #pragma unroll
    for (int kk = 0; kk < 9; kk++) {
        const size_t off = rb + kk * 64 + 2 * lane;
        __nv_bfloat162 hh, ll;
        hh.x = __float2bfloat16(u[kk].x); hh.y = __float2bfloat16(u[kk].y);
        ll.x = __float2bfloat16(u[kk].x - __bfloat162float(hh.x));
        ll.y = __float2bfloat16(u[kk].y - __bfloat162float(hh.y));
        *reinterpret_cast<__nv_bfloat162*>(&g_A[0][off]) = hh;
        *reinterpret_cast<__nv_bfloat162*>(&g_A[1][off]) = ll;
        hh.x = __float2bfloat16(w[kk].x); hh.y = __float2bfloat16(w[kk].y);
        ll.x = __float2bfloat16(w[kk].x - __bfloat162float(hh.x));
        ll.y = __float2bfloat16(w[kk].y - __bfloat162float(hh.y));
        *reinterpret_cast<__nv_bfloat162*>(&g_A[2][off]) = hh;
        *reinterpret_cast<__nv_bfloat162*>(&g_A[3][off]) = ll;
    }
    if (lane == 0) {
        g_imp[n] = impacc;
        out[(size_t)N_OUT * CO + n] = impacc;   // imp_sum output
    }
}

// ---------------------------------------------------------------------------
// Kernel 4: HMMA GEMM. 4-slot cp.async pipeline, KCH=16, one barrier/chunk,
// 3-chunk prefetch. Slot (24KB): [Auh|Aul|Awh|Awl|Bh|Bl] x 4KB, 32B rows,
// sw32 swizzle. Warps: 2(M64) x 4(N32); w_n<3 -> Au, w_n==3 -> Aw.
// ---------------------------------------------------------------------------
extern __shared__ __align__(128) char gsm[];

__global__ __launch_bounds__(256, 2)
void gemm_kernel(const float* __restrict__ b_a,
                 const float* __restrict__ b_b,
                 float*       __restrict__ out) {
    const int tid = threadIdx.x, lane = tid & 31, wid = tid >> 5;
    const int w_m = wid & 1, w_n = wid >> 1;
    const int g = lane >> 2, tig = lane & 3;
    const size_t mtile = (size_t)blockIdx.x * MTILE;
    const uint32_t sbase = smem_u32(gsm);

    // cp.async geometry: one 16B copy per array per thread
    const int row = tid >> 1, cc = tid & 1;
    const int aIdx = (int)((mtile + row) * KHALF + cc * 8);
    const int bIdx = row * KHALF + cc * 8;
    const uint32_t dOff = sw32((uint32_t)(row * 32 + cc * 16));

    // ldmatrix per-lane swizzled base offsets (offsets of +512/+4096 commute
    // with sw32 since it only touches bits [4:6])
    const uint32_t aOff = sw32((uint32_t)((w_m * 64 + (lane & 15)) * 32
                                          + ((lane >> 4) & 1) * 16));
    const uint32_t bOff = sw32((uint32_t)((w_n * 32 + (lane & 7)
                                          + ((lane >> 4) & 1) * 8) * 32
                                          + ((lane >> 3) & 1) * 16));
    const uint32_t ahSel = (w_n < 3) ? 0u : 8192u;

    float acc[4][4][4];
    #pragma unroll
    for (int i = 0; i < 4; i++)
        #pragma unroll
        for (int j = 0; j < 4; j++)
            #pragma unroll
            for (int q = 0; q < 4; q++) acc[i][j][q] = 0.f;

    auto issue = [&](int c) {
        const uint32_t st = sbase + (uint32_t)(c & 3) * SLOT;
        const int k0 = c * KCH;
        #pragma unroll
        for (int arr = 0; arr < 4; arr++)
            cp16(st + arr * 4096 + dOff, &g_A[arr][0] + aIdx + k0);
        #pragma unroll
        for (int arr = 0; arr < 2; arr++)
            cp16(st + 16384 + arr * 4096 + dOff, &g_B[arr][0] + bIdx + k0);
        CP_COMMIT;
    };

    issue(0); issue(1); issue(2);

    for (int c = 0; c < NCHUNK; c++) {
        if (c < NCHUNK - 2)       asm volatile("cp.async.wait_group 2;" ::: "memory");
        else if (c == NCHUNK - 2) asm volatile("cp.async.wait_group 1;" ::: "memory");
        else                      asm volatile("cp.async.wait_group 0;" ::: "memory");
        __syncthreads();
        if (c + 3 < NCHUNK) issue(c + 3);

        const uint32_t st  = sbase + (uint32_t)(c & 3) * SLOT;
        const uint32_t sAh = st + ahSel;
        const uint32_t sAl = sAh + 4096;
        const uint32_t sBh = st + 16384;
        const uint32_t sBl = st + 20480;

        uint32_t bh[8], bl[8];
        ldm4(bh[0], bh[1], bh[2], bh[3], sBh + bOff);
        ldm4(bh[4], bh[5], bh[6], bh[7], sBh + bOff + 512);
        ldm4(bl[0], bl[1], bl[2], bl[3], sBl + bOff);
        ldm4(bl[4], bl[5], bl[6], bl[7], sBl + bOff + 512);
        #pragma unroll
        for (int mf = 0; mf < 4; mf++) {
            uint32_t ah[4], al[4];
            ldm4(ah[0], ah[1], ah[2], ah[3], sAh + aOff + mf * 512);
            ldm4(al[0], al[1], al[2], al[3], sAl + aOff + mf * 512);
            #pragma unroll
            for (int nf = 0; nf < 4; nf++) {
                mma_bf16(acc[mf][nf], ah, bh[2 * nf], bh[2 * nf + 1]);
                mma_bf16(acc[mf][nf], ah, bl[2 * nf], bl[2 * nf + 1]);
                mma_bf16(acc[mf][nf], al, bh[2 * nf], bh[2 * nf + 1]);
            }
        }
    }

    // ---- epilogue: bias / normalize / relu / store ----
    float bias[4][2];
    #pragma unroll
    for (int nf = 0; nf < 4; nf++) {
        const int col = w_n * 32 + nf * 8 + 2 * tig;
        bias[nf][0] = (col < 96) ? __ldg(b_a + col)     : __ldg(b_b + col - 96);
        bias[nf][1] = (col < 96) ? __ldg(b_a + col + 1) : __ldg(b_b + col - 95);
    }

    #pragma unroll
    for (int mf = 0; mf < 4; mf++) {
        #pragma unroll
        for (int half = 0; half < 2; half++) {
            const int n = (int)mtile + w_m * 64 + mf * 16 + g + half * 8;
            if (n >= N_OUT) continue;
            float inv = 1.f;
            if (w_n == 3) inv = 1.f / fmaxf(__ldg(g_imp + n), 1e-8f);
            #pragma unroll
            for (int nf = 0; nf < 4; nf++) {
                const int col = w_n * 32 + nf * 8 + 2 * tig;
                float2 r;
                r.x = fmaxf(fmaf(acc[mf][nf][half * 2 + 0], inv, bias[nf][0]), 0.f);
                r.y = fmaxf(fmaf(acc[mf][nf][half * 2 + 1], inv, bias[nf][1]), 0.f);
                *reinterpret_cast<float2*>(out + (size_t)n * CO + col) = r;
            }
        }
    }
}

// ---------------------------------------------------------------------------
extern "C" void kernel_launch(void* const* d_in, const int* in_sizes, int n_in,
                              void* d_out, int out_size) {
    const float* feats      = (const float*)d_in[0];
    const float* importance = (const float*)d_in[1];
    const float* W_a        = (const float*)d_in[2];
    const float* b_a        = (const float*)d_in[3];
    const float* W_b        = (const float*)d_in[4];
    const float* b_b        = (const float*)d_in[5];
    const int*   nbr        = (const int*)d_in[6];
    const int*   kid        = (const int*)d_in[7];
    const int*   oid        = (const int*)d_in[8];
    float*       out        = (float*)d_out;

    build_offsets_kernel<<<(NE + 255) / 256, 256>>>(oid);
    build_w_kernel<<<(CO * KHALF + 255) / 256, 256>>>(W_a, W_b);
    bin_kernel<<<N_OUT / 8, 256>>>(feats, importance, nbr, kid, out);

    const int smem_bytes = 4 * SLOT;   // 98,304 B
    cudaFuncSetAttribute(gemm_kernel,
                         cudaFuncAttributeMaxDynamicSharedMemorySize, smem_bytes);
    gemm_kernel<<<NTILES, 256, smem_bytes>>>(b_a, b_b, out);
}

// round 6
// speedup vs baseline: 1.2643x; 1.2643x over previous
#include <cuda_runtime.h>
#include <cuda_bf16.h>
#include <cstdint>

// ---------------- problem constants ----------------
#define N_IN   200000
#define N_OUT  100000
#define NE     1600000
#define CIN    64
#define CO     128
#define KHALF  576
#define MTILE  128
#define MPAD   100096          // 782 * 128
#define NTILES 782
#define KCH    32              // K elems per pipeline chunk
#define NCHUNK 18              // 576 / 32
#define SLOT   32768           // 4 A-arrays x [128][32] bf16 (8KB each)
#define NSTEPS 36              // 576 / 16 k16-steps

#define ASZ    ((size_t)MPAD * KHALF)

// ---------------- device scratch (no allocs allowed) ----------------
__device__ int            g_offs[N_OUT + 1];
__device__ float          g_imp[N_OUT];
// A arrays: 0=Auh 1=Aul 2=Awh 3=Awl ; padded rows stay zero (.bss)
__device__ __nv_bfloat16  g_A[4][ASZ];
// B pre-packed in mma fragment order: [arr(h/l)][k16-step][w_n][lane][8]
__device__ uint32_t       g_Bp[2 * NSTEPS * 4 * 32 * 8];

// ---------------- helpers ----------------
__device__ __forceinline__ uint32_t smem_u32(const void* p) {
    uint32_t a;
    asm("{ .reg .u64 t; cvta.to.shared.u64 t, %1; cvt.u32.u64 %0, t; }"
        : "=r"(a) : "l"(p));
    return a;
}
__device__ __forceinline__ uint32_t sw64(uint32_t o) {   // 64B-row swizzle
    return o ^ ((o >> 3) & 0x30);
}
__device__ __forceinline__ void cp16(uint32_t dst, const void* src) {
    asm volatile("cp.async.cg.shared.global [%0], [%1], 16;" :: "r"(dst), "l"(src));
}
#define CP_COMMIT asm volatile("cp.async.commit_group;" ::: "memory")

__device__ __forceinline__ void ldm4(uint32_t& r0, uint32_t& r1,
                                     uint32_t& r2, uint32_t& r3, uint32_t a) {
    asm volatile("ldmatrix.sync.aligned.m8n8.x4.shared.b16 {%0,%1,%2,%3}, [%4];"
                 : "=r"(r0), "=r"(r1), "=r"(r2), "=r"(r3) : "r"(a));
}
__device__ __forceinline__ void mma_bf16(float* c, const uint32_t* a,
                                         uint32_t b0, uint32_t b1) {
    asm volatile(
        "mma.sync.aligned.m16n8k16.row.col.f32.bf16.bf16.f32 "
        "{%0,%1,%2,%3}, {%4,%5,%6,%7}, {%8,%9}, {%0,%1,%2,%3};"
        : "+f"(c[0]), "+f"(c[1]), "+f"(c[2]), "+f"(c[3])
        : "r"(a[0]), "r"(a[1]), "r"(a[2]), "r"(a[3]), "r"(b0), "r"(b1));
}

// ---------------------------------------------------------------------------
// Kernel 1: CSR offsets via adjacent-diff over sorted neighbors_out_index
// ---------------------------------------------------------------------------
__global__ void build_offsets_kernel(const int* __restrict__ out_idx) {
    int e = blockIdx.x * blockDim.x + threadIdx.x;
    if (e >= NE) return;
    int b = __ldg(out_idx + e);
    int a = (e == 0) ? -1 : __ldg(out_idx + e - 1);
    for (int n = a + 1; n <= b; n++) g_offs[n] = e;
    if (e == NE - 1)
        for (int n = b + 1; n <= N_OUT; n++) g_offs[n] = NE;
}

// ---------------------------------------------------------------------------
// Kernel 2: pack weights straight into mma-fragment order, bf16 hi/lo.
// Index i -> [arr][s][wn][lane][j], j = nf*2 + r:
//   col = wn*32 + nf*8 + (lane>>2)
//   k   = s*16 + (lane&3)*2 + r*8      (pair k, k+1 in one bf16x2)
// ---------------------------------------------------------------------------
__global__ void build_bp_kernel(const float* __restrict__ Wa,
                                const float* __restrict__ Wb) {
    int i = blockIdx.x * blockDim.x + threadIdx.x;
    if (i >= 2 * NSTEPS * 4 * 32 * 8) return;
    const int arr  = i / (NSTEPS * 1024);
    const int rem  = i % (NSTEPS * 1024);
    const int s    = rem / 1024;
    const int wn   = (rem % 1024) / 256;
    const int lane = (rem % 256) / 8;
    const int j    = rem % 8;
    const int nf = j >> 1, r = j & 1;
    const int col = wn * 32 + nf * 8 + (lane >> 2);
    const int k   = s * 16 + (lane & 3) * 2 + r * 8;
    float v0, v1;
    if (col < 96) { v0 = __ldg(Wa + k * 96 + col); v1 = __ldg(Wa + (k + 1) * 96 + col); }
    else          { v0 = __ldg(Wb + k * 32 + col - 96); v1 = __ldg(Wb + (k + 1) * 32 + col - 96); }
    __nv_bfloat16 h0 = __float2bfloat16(v0);
    __nv_bfloat16 h1 = __float2bfloat16(v1);
    __nv_bfloat16 x0 = h0, x1 = h1;
    if (arr == 1) {
        x0 = __float2bfloat16(v0 - __bfloat162float(h0));
        x1 = __float2bfloat16(v1 - __bfloat162float(h1));
    }
    g_Bp[i] = ((uint32_t)__bfloat16_as_ushort(x1) << 16) | __bfloat16_as_ushort(x0);
}

// ---------------------------------------------------------------------------
// Kernel 3: binning (round-4 proven version). One warp per output point;
// fp32 bins in smem; bf16 hi/lo split streamed to global staging (__stcs).
// ---------------------------------------------------------------------------
__global__ __launch_bounds__(256)
void bin_kernel(const float* __restrict__ feats,
                const float* __restrict__ importance,
                const int*   __restrict__ nbr,
                const int*   __restrict__ kid,
                float*       __restrict__ out) {
    __shared__ float sb[8][1152];
    const int lane = threadIdx.x & 31;
    const int w    = threadIdx.x >> 5;
    const int n    = blockIdx.x * 8 + w;

    float*  b  = sb[w];
    float2* b2 = reinterpret_cast<float2*>(b);
    float4* bz = reinterpret_cast<float4*>(b);
    #pragma unroll
    for (int i = lane; i < 1152 / 4; i += 32) bz[i] = make_float4(0.f, 0.f, 0.f, 0.f);
    __syncwarp();

    const int e0 = g_offs[n], e1 = g_offs[n + 1];
    float impacc = 0.f;
    for (int e = e0; e < e1; e++) {
        const int    src = __ldg(nbr + e);
        const int    k   = __ldg(kid + e);
        const float  im  = __ldg(importance + src);
        const float2 f   = *reinterpret_cast<const float2*>(
                               feats + (size_t)src * CIN + 2 * lane);
        const int o2 = k * 32 + lane;
        float2 bu = b2[o2];
        bu.x += f.x; bu.y += f.y;
        b2[o2] = bu;
        float2 bw = b2[288 + o2];
        bw.x = fmaf(f.x, im, bw.x); bw.y = fmaf(f.y, im, bw.y);
        b2[288 + o2] = bw;
        impacc += im;
    }
    __syncwarp();

    const size_t base = (size_t)n * KHALF;
    #pragma unroll
    for (int j = 0; j < KHALF; j += 64) {
        const int kc = j + 2 * lane;
        {   // u half -> g_A[0]/g_A[1]
            float2 v = *reinterpret_cast<float2*>(b + kc);
            __nv_bfloat162 hh, ll;
            hh.x = __float2bfloat16(v.x); hh.y = __float2bfloat16(v.y);
            ll.x = __float2bfloat16(v.x - __bfloat162float(hh.x));
            ll.y = __float2bfloat16(v.y - __bfloat162float(hh.y));
            __stcs(reinterpret_cast<uint32_t*>(&g_A[0][base + kc]),
                   *reinterpret_cast<uint32_t*>(&hh));
            __stcs(reinterpret_cast<uint32_t*>(&g_A[1][base + kc]),
                   *reinterpret_cast<uint32_t*>(&ll));
        }
        {   // w half -> g_A[2]/g_A[3]
            float2 v = *reinterpret_cast<float2*>(b + 576 + kc);
            __nv_bfloat162 hh, ll;
            hh.x = __float2bfloat16(v.x); hh.y = __float2bfloat16(v.y);
            ll.x = __float2bfloat16(v.x - __bfloat162float(hh.x));
            ll.y = __float2bfloat16(v.y - __bfloat162float(hh.y));
            __stcs(reinterpret_cast<uint32_t*>(&g_A[2][base + kc]),
                   *reinterpret_cast<uint32_t*>(&hh));
            __stcs(reinterpret_cast<uint32_t*>(&g_A[3][base + kc]),
                   *reinterpret_cast<uint32_t*>(&ll));
        }
    }
    if (lane == 0) {
        g_imp[n] = impacc;
        out[(size_t)N_OUT * CO + n] = impacc;   // imp_sum output
    }
}

// ---------------------------------------------------------------------------
// Kernel 4: HMMA GEMM. A via 3-stage cp.async pipeline (depth-2 prefetch,
// 32KB/stage), B via direct LDG of pre-packed fragments (L2-resident).
// Warps: 2(M64) x 4(N32); w_n<3 -> Au, w_n==3 -> Aw. 2 CTAs/SM.
// ---------------------------------------------------------------------------
extern __shared__ __align__(128) char gsm[];

__global__ __launch_bounds__(256, 2)
void gemm_kernel(const float* __restrict__ b_a,
                 const float* __restrict__ b_b,
                 float*       __restrict__ out) {
    const int tid = threadIdx.x, lane = tid & 31, wid = tid >> 5;
    const int w_m = wid & 1, w_n = wid >> 1;
    const int g = lane >> 2, tig = lane & 3;
    const size_t mtile = (size_t)blockIdx.x * MTILE;
    const uint32_t sbase = smem_u32(gsm);

    // cp.async geometry: 2 x 16B per thread per A array (128 rows x 4 cols)
    int   aIdx[2];
    uint32_t dOff[2];
    #pragma unroll
    for (int q = 0; q < 2; q++) {
        const int idx = q * 256 + tid;      // 0..511
        const int row = idx >> 2, c = idx & 3;
        aIdx[q] = (int)((mtile + row) * KHALF + c * 8);
        dOff[q] = sw64(row * 64 + c * 16);
    }

    // ldmatrix per-lane base offset (A), 64B rows
    const uint32_t aOffB = (uint32_t)(w_m * 64 + (lane & 15)) * 64
                         + ((lane >> 4) & 1) * 16;
    const uint32_t ahSel = (w_n < 3) ? 0u : 16384u;   // Auh vs Awh

    // B fragment pointers (per warp n-tile, per lane)
    const uint32_t* bpH = g_Bp + (0 * NSTEPS * 4 + w_n) * 256 + lane * 8;
    const uint32_t* bpL = bpH + NSTEPS * 4 * 256;

    float acc[4][4][4];
    #pragma unroll
    for (int i = 0; i < 4; i++)
        #pragma unroll
        for (int j = 0; j < 4; j++)
            #pragma unroll
            for (int q = 0; q < 4; q++) acc[i][j][q] = 0.f;

    auto issue = [&](int c) {
        const uint32_t st = sbase + (uint32_t)(c % 3) * SLOT;
        const int k0 = c * KCH;
        #pragma unroll
        for (int q = 0; q < 2; q++)
            #pragma unroll
            for (int arr = 0; arr < 4; arr++)
                cp16(st + arr * 8192 + dOff[q], &g_A[arr][0] + aIdx[q] + k0);
        CP_COMMIT;
    };

    issue(0); issue(1); issue(2);

    for (int c = 0; c < NCHUNK; c++) {
        if (c <= NCHUNK - 3)      asm volatile("cp.async.wait_group 2;" ::: "memory");
        else if (c == NCHUNK - 2) asm volatile("cp.async.wait_group 1;" ::: "memory");
        else                      asm volatile("cp.async.wait_group 0;" ::: "memory");
        __syncthreads();

        const uint32_t st  = sbase + (uint32_t)(c % 3) * SLOT;
        const uint32_t sAh = st + ahSel;
        const uint32_t sAl = sAh + 8192;

        #pragma unroll
        for (int ks = 0; ks < 2; ks++) {
            const int s = 2 * c + ks;
            uint32_t bh[8], bl[8];
            *reinterpret_cast<uint4*>(bh)     = *reinterpret_cast<const uint4*>(bpH + s * 1024);
            *reinterpret_cast<uint4*>(bh + 4) = *reinterpret_cast<const uint4*>(bpH + s * 1024 + 4);
            *reinterpret_cast<uint4*>(bl)     = *reinterpret_cast<const uint4*>(bpL + s * 1024);
            *reinterpret_cast<uint4*>(bl + 4) = *reinterpret_cast<const uint4*>(bpL + s * 1024 + 4);
            #pragma unroll
            for (int mf = 0; mf < 4; mf++) {
                const uint32_t ao = sw64(aOffB + mf * 1024 + ks * 32);
                uint32_t ah[4], al[4];
                ldm4(ah[0], ah[1], ah[2], ah[3], sAh + ao);
                ldm4(al[0], al[1], al[2], al[3], sAl + ao);
                #pragma unroll
                for (int nf = 0; nf < 4; nf++) {
                    mma_bf16(acc[mf][nf], ah, bh[2 * nf], bh[2 * nf + 1]);
                    mma_bf16(acc[mf][nf], ah, bl[2 * nf], bl[2 * nf + 1]);
                    mma_bf16(acc[mf][nf], al, bh[2 * nf], bh[2 * nf + 1]);
                }
            }
        }
        __syncthreads();
        if (c + 3 < NCHUNK) issue(c + 3);
    }

    // ---- epilogue: bias / normalize / relu / store ----
    float bias[4][2];
    #pragma unroll
    for (int nf = 0; nf < 4; nf++) {
        const int col = w_n * 32 + nf * 8 + 2 * tig;
        bias[nf][0] = (col < 96) ? __ldg(b_a + col)     : __ldg(b_b + col - 96);
        bias[nf][1] = (col < 96) ? __ldg(b_a + col + 1) : __ldg(b_b + col - 95);
    }

    #pragma unroll
    for (int mf = 0; mf < 4; mf++) {
        #pragma unroll
        for (int half = 0; half < 2; half++) {
            const int n = (int)mtile + w_m * 64 + mf * 16 + g + half * 8;
            if (n >= N_OUT) continue;
            float inv = 1.f;
            if (w_n == 3) inv = 1.f / fmaxf(__ldg(g_imp + n), 1e-8f);
            #pragma unroll
            for (int nf = 0; nf < 4; nf++) {
                const int col = w_n * 32 + nf * 8 + 2 * tig;
                float2 r;
                r.x = fmaxf(fmaf(acc[mf][nf][half * 2 + 0], inv, bias[nf][0]), 0.f);
                r.y = fmaxf(fmaf(acc[mf][nf][half * 2 + 1], inv, bias[nf][1]), 0.f);
                *reinterpret_cast<float2*>(out + (size_t)n * CO + col) = r;
            }
        }
    }
}

// ---------------------------------------------------------------------------
extern "C" void kernel_launch(void* const* d_in, const int* in_sizes, int n_in,
                              void* d_out, int out_size) {
    const float* feats      = (const float*)d_in[0];
    const float* importance = (const float*)d_in[1];
    const float* W_a        = (const float*)d_in[2];
    const float* b_a        = (const float*)d_in[3];
    const float* W_b        = (const float*)d_in[4];
    const float* b_b        = (const float*)d_in[5];
    const int*   nbr        = (const int*)d_in[6];
    const int*   kid        = (const int*)d_in[7];
    const int*   oid        = (const int*)d_in[8];
    float*       out        = (float*)d_out;

    build_offsets_kernel<<<(NE + 255) / 256, 256>>>(oid);
    build_bp_kernel<<<(2 * NSTEPS * 4 * 32 * 8 + 255) / 256, 256>>>(W_a, W_b);
    bin_kernel<<<N_OUT / 8, 256>>>(feats, importance, nbr, kid, out);

    const int smem_bytes = 3 * SLOT;   // 98,304 B
    cudaFuncSetAttribute(gemm_kernel,
                         cudaFuncAttributeMaxDynamicSharedMemorySize, smem_bytes);
    gemm_kernel<<<NTILES, 256, smem_bytes>>>(b_a, b_b, out);
}

// round 7
// speedup vs baseline: 1.2738x; 1.0075x over previous
#include <cuda_runtime.h>
#include <cuda_bf16.h>
#include <cstdint>

// ---------------- problem constants ----------------
#define N_IN   200000
#define N_OUT  100000
#define NE     1600000
#define CIN    64
#define CO     128
#define KHALF  576
#define MTILE  128
#define MPAD   100096          // 782 * 128
#define NTILES 782
#define KCH    32              // K elems per pipeline chunk
#define NCHUNK 18              // 576 / 32
#define SLOT   32768           // 4 A-arrays x [128][32] bf16 (8KB each)
#define NSTEPS 36              // 576 / 16 k16-steps

#define ASZ    ((size_t)MPAD * KHALF)

// ---------------- device scratch (no allocs allowed) ----------------
__device__ int            g_offs[N_OUT + 1];
__device__ float          g_imp[N_OUT];
// A arrays: 0=Auh 1=Aul 2=Awh 3=Awl ; padded rows stay zero (.bss)
__device__ __nv_bfloat16  g_A[4][ASZ];
// B pre-packed in mma fragment order: [arr(h/l)][k16-step][w_n][lane][8]
__device__ uint32_t       g_Bp[2 * NSTEPS * 4 * 32 * 8];

// ---------------- helpers ----------------
__device__ __forceinline__ uint32_t smem_u32(const void* p) {
    uint32_t a;
    asm("{ .reg .u64 t; cvta.to.shared.u64 t, %1; cvt.u32.u64 %0, t; }"
        : "=r"(a) : "l"(p));
    return a;
}
__device__ __forceinline__ uint32_t sw64(uint32_t o) {   // 64B-row swizzle
    return o ^ ((o >> 3) & 0x30);
}
__device__ __forceinline__ void cp16(uint32_t dst, const void* src) {
    asm volatile("cp.async.cg.shared.global [%0], [%1], 16;" :: "r"(dst), "l"(src));
}
#define CP_COMMIT asm volatile("cp.async.commit_group;" ::: "memory")

__device__ __forceinline__ void ldm4(uint32_t& r0, uint32_t& r1,
                                     uint32_t& r2, uint32_t& r3, uint32_t a) {
    asm volatile("ldmatrix.sync.aligned.m8n8.x4.shared.b16 {%0,%1,%2,%3}, [%4];"
                 : "=r"(r0), "=r"(r1), "=r"(r2), "=r"(r3) : "r"(a));
}
__device__ __forceinline__ void mma_bf16(float* c, const uint32_t* a,
                                         uint32_t b0, uint32_t b1) {
    asm volatile(
        "mma.sync.aligned.m16n8k16.row.col.f32.bf16.bf16.f32 "
        "{%0,%1,%2,%3}, {%4,%5,%6,%7}, {%8,%9}, {%0,%1,%2,%3};"
        : "+f"(c[0]), "+f"(c[1]), "+f"(c[2]), "+f"(c[3])
        : "r"(a[0]), "r"(a[1]), "r"(a[2]), "r"(a[3]), "r"(b0), "r"(b1));
}

// ---------------------------------------------------------------------------
// Kernel 1: CSR offsets via adjacent-diff over sorted neighbors_out_index
// ---------------------------------------------------------------------------
__global__ void build_offsets_kernel(const int* __restrict__ out_idx) {
    int e = blockIdx.x * blockDim.x + threadIdx.x;
    if (e >= NE) return;
    int b = __ldg(out_idx + e);
    int a = (e == 0) ? -1 : __ldg(out_idx + e - 1);
    for (int n = a + 1; n <= b; n++) g_offs[n] = e;
    if (e == NE - 1)
        for (int n = b + 1; n <= N_OUT; n++) g_offs[n] = NE;
}

// ---------------------------------------------------------------------------
// Kernel 2: pack weights straight into mma-fragment order, bf16 hi/lo.
//   col = wn*32 + nf*8 + (lane>>2)
//   k   = s*16 + (lane&3)*2 + r*8
// ---------------------------------------------------------------------------
__global__ void build_bp_kernel(const float* __restrict__ Wa,
                                const float* __restrict__ Wb) {
    int i = blockIdx.x * blockDim.x + threadIdx.x;
    if (i >= 2 * NSTEPS * 4 * 32 * 8) return;
    const int arr  = i / (NSTEPS * 1024);
    const int rem  = i % (NSTEPS * 1024);
    const int s    = rem / 1024;
    const int wn   = (rem % 1024) / 256;
    const int lane = (rem % 256) / 8;
    const int j    = rem % 8;
    const int nf = j >> 1, r = j & 1;
    const int col = wn * 32 + nf * 8 + (lane >> 2);
    const int k   = s * 16 + (lane & 3) * 2 + r * 8;
    float v0, v1;
    if (col < 96) { v0 = __ldg(Wa + k * 96 + col); v1 = __ldg(Wa + (k + 1) * 96 + col); }
    else          { v0 = __ldg(Wb + k * 32 + col - 96); v1 = __ldg(Wb + (k + 1) * 32 + col - 96); }
    __nv_bfloat16 h0 = __float2bfloat16(v0);
    __nv_bfloat16 h1 = __float2bfloat16(v1);
    __nv_bfloat16 x0 = h0, x1 = h1;
    if (arr == 1) {
        x0 = __float2bfloat16(v0 - __bfloat162float(h0));
        x1 = __float2bfloat16(v1 - __bfloat162float(h1));
    }
    g_Bp[i] = ((uint32_t)__bfloat16_as_ushort(x1) << 16) | __bfloat16_as_ushort(x0);
}

// ---------------------------------------------------------------------------
// Kernel 3: binning. One warp per output point; fp32 bins in smem;
// bf16 hi/lo split streamed to global staging.
// ---------------------------------------------------------------------------
__global__ __launch_bounds__(256)
void bin_kernel(const float* __restrict__ feats,
                const float* __restrict__ importance,
                const int*   __restrict__ nbr,
                const int*   __restrict__ kid,
                float*       __restrict__ out) {
    __shared__ float sb[8][1152];
    const int lane = threadIdx.x & 31;
    const int w    = threadIdx.x >> 5;
    const int n    = blockIdx.x * 8 + w;

    float*  b  = sb[w];
    float2* b2 = reinterpret_cast<float2*>(b);
    float4* bz = reinterpret_cast<float4*>(b);
    #pragma unroll
    for (int i = lane; i < 1152 / 4; i += 32) bz[i] = make_float4(0.f, 0.f, 0.f, 0.f);
    __syncwarp();

    const int e0 = g_offs[n], e1 = g_offs[n + 1];
    float impacc = 0.f;
    #pragma unroll 2
    for (int e = e0; e < e1; e++) {
        const int    src = __ldg(nbr + e);
        const int    k   = __ldg(kid + e);
        const float  im  = __ldg(importance + src);
        const float2 f   = *reinterpret_cast<const float2*>(
                               feats + (size_t)src * CIN + 2 * lane);
        const int o2 = k * 32 + lane;
        float2 bu = b2[o2];
        bu.x += f.x; bu.y += f.y;
        b2[o2] = bu;
        float2 bw = b2[288 + o2];
        bw.x = fmaf(f.x, im, bw.x); bw.y = fmaf(f.y, im, bw.y);
        b2[288 + o2] = bw;
        impacc += im;
    }
    __syncwarp();

    const size_t base = (size_t)n * KHALF;
    #pragma unroll
    for (int j = 0; j < KHALF; j += 64) {
        const int kc = j + 2 * lane;
        {   // u half -> g_A[0]/g_A[1]
            float2 v = *reinterpret_cast<float2*>(b + kc);
            __nv_bfloat162 hh, ll;
            hh.x = __float2bfloat16(v.x); hh.y = __float2bfloat16(v.y);
            ll.x = __float2bfloat16(v.x - __bfloat162float(hh.x));
            ll.y = __float2bfloat16(v.y - __bfloat162float(hh.y));
            __stcs(reinterpret_cast<uint32_t*>(&g_A[0][base + kc]),
                   *reinterpret_cast<uint32_t*>(&hh));
            __stcs(reinterpret_cast<uint32_t*>(&g_A[1][base + kc]),
                   *reinterpret_cast<uint32_t*>(&ll));
        }
        {   // w half -> g_A[2]/g_A[3]
            float2 v = *reinterpret_cast<float2*>(b + 576 + kc);
            __nv_bfloat162 hh, ll;
            hh.x = __float2bfloat16(v.x); hh.y = __float2bfloat16(v.y);
            ll.x = __float2bfloat16(v.x - __bfloat162float(hh.x));
            ll.y = __float2bfloat16(v.y - __bfloat162float(hh.y));
            __stcs(reinterpret_cast<uint32_t*>(&g_A[2][base + kc]),
                   *reinterpret_cast<uint32_t*>(&hh));
            __stcs(reinterpret_cast<uint32_t*>(&g_A[3][base + kc]),
                   *reinterpret_cast<uint32_t*>(&ll));
        }
    }
    if (lane == 0) {
        g_imp[n] = impacc;
        out[(size_t)N_OUT * CO + n] = impacc;   // imp_sum output
    }
}

// ---------------------------------------------------------------------------
// Kernel 4: HMMA GEMM. A via 3-stage cp.async pipeline (depth-2, 32KB/stage,
// ONE barrier per chunk, issue(c+2) right after the sync — race-free since
// stage (c+2)%3 was chunk c-1's, whose readers all passed this barrier).
// B via register-double-buffered LDG of pre-packed fragments (prefetched one
// k16-step ahead, L2 latency hidden under 48 MMAs). 2 CTAs/SM.
// ---------------------------------------------------------------------------
extern __shared__ __align__(128) char gsm[];

__global__ __launch_bounds__(256, 2)
void gemm_kernel(const float* __restrict__ b_a,
                 const float* __restrict__ b_b,
                 float*       __restrict__ out) {
    const int tid = threadIdx.x, lane = tid & 31, wid = tid >> 5;
    const int w_m = wid & 1, w_n = wid >> 1;
    const int g = lane >> 2, tig = lane & 3;
    const size_t mtile = (size_t)blockIdx.x * MTILE;
    const uint32_t sbase = smem_u32(gsm);

    // cp.async geometry: 2 x 16B per thread per A array (128 rows x 4 cols)
    int   aIdx[2];
    uint32_t dOff[2];
    #pragma unroll
    for (int q = 0; q < 2; q++) {
        const int idx = q * 256 + tid;      // 0..511
        const int row = idx >> 2, c = idx & 3;
        aIdx[q] = (int)((mtile + row) * KHALF + c * 8);
        dOff[q] = sw64(row * 64 + c * 16);
    }

    // ldmatrix per-lane base offset (A), 64B rows
    const uint32_t aOffB = (uint32_t)(w_m * 64 + (lane & 15)) * 64
                         + ((lane >> 4) & 1) * 16;
    const uint32_t ahSel = (w_n < 3) ? 0u : 16384u;   // Auh vs Awh

    // B fragment pointers (per warp n-tile, per lane)
    const uint32_t* bpH = g_Bp + w_n * 256 + lane * 8;
    const uint32_t* bpL = bpH + NSTEPS * 4 * 256;

    float acc[4][4][4];
    #pragma unroll
    for (int i = 0; i < 4; i++)
        #pragma unroll
        for (int j = 0; j < 4; j++)
            #pragma unroll
            for (int q = 0; q < 4; q++) acc[i][j][q] = 0.f;

    auto issue = [&](int c) {
        const uint32_t st = sbase + (uint32_t)(c % 3) * SLOT;
        const int k0 = c * KCH;
        #pragma unroll
        for (int q = 0; q < 2; q++)
            #pragma unroll
            for (int arr = 0; arr < 4; arr++)
                cp16(st + arr * 8192 + dOff[q], &g_A[arr][0] + aIdx[q] + k0);
        CP_COMMIT;
    };

    // B register double buffer: breg[par][0..7]=bh, [8..15]=bl, par = s&1 = ks
    uint32_t breg[2][16];
    auto loadB = [&](int s, uint32_t* d) {
        const uint32_t* ph = bpH + (size_t)s * 1024;
        const uint32_t* pl = bpL + (size_t)s * 1024;
        *reinterpret_cast<uint4*>(d)      = __ldg(reinterpret_cast<const uint4*>(ph));
        *reinterpret_cast<uint4*>(d + 4)  = __ldg(reinterpret_cast<const uint4*>(ph + 4));
        *reinterpret_cast<uint4*>(d + 8)  = __ldg(reinterpret_cast<const uint4*>(pl));
        *reinterpret_cast<uint4*>(d + 12) = __ldg(reinterpret_cast<const uint4*>(pl + 4));
    };

    issue(0); issue(1);
    loadB(0, breg[0]);

    for (int c = 0; c < NCHUNK; c++) {
        if (c + 1 < NCHUNK) asm volatile("cp.async.wait_group 1;" ::: "memory");
        else                asm volatile("cp.async.wait_group 0;" ::: "memory");
        __syncthreads();
        if (c + 2 < NCHUNK) issue(c + 2);

        const uint32_t st  = sbase + (uint32_t)(c % 3) * SLOT;
        const uint32_t sAh = st + ahSel;
        const uint32_t sAl = sAh + 8192;

        #pragma unroll
        for (int ks = 0; ks < 2; ks++) {
            const int s = 2 * c + ks;
            // prefetch next step's B into the other buffer (hidden under MMAs)
            if (s + 1 < 2 * NCHUNK) loadB(s + 1, breg[ks ^ 1]);
            const uint32_t* bh = breg[ks];
            const uint32_t* bl = breg[ks] + 8;
            #pragma unroll
            for (int mf = 0; mf < 4; mf++) {
                const uint32_t ao = sw64(aOffB + mf * 1024 + ks * 32);
                uint32_t ah[4], al[4];
                ldm4(ah[0], ah[1], ah[2], ah[3], sAh + ao);
                ldm4(al[0], al[1], al[2], al[3], sAl + ao);
                #pragma unroll
                for (int nf = 0; nf < 4; nf++) {
                    mma_bf16(acc[mf][nf], ah, bh[2 * nf], bh[2 * nf + 1]);
                    mma_bf16(acc[mf][nf], ah, bl[2 * nf], bl[2 * nf + 1]);
                    mma_bf16(acc[mf][nf], al, bh[2 * nf], bh[2 * nf + 1]);
                }
            }
        }
    }

    // ---- epilogue: bias / normalize / relu / store ----
    float bias[4][2];
    #pragma unroll
    for (int nf = 0; nf < 4; nf++) {
        const int col = w_n * 32 + nf * 8 + 2 * tig;
        bias[nf][0] = (col < 96) ? __ldg(b_a + col)     : __ldg(b_b + col - 96);
        bias[nf][1] = (col < 96) ? __ldg(b_a + col + 1) : __ldg(b_b + col - 95);
    }

    #pragma unroll
    for (int mf = 0; mf < 4; mf++) {
        #pragma unroll
        for (int half = 0; half < 2; half++) {
            const int n = (int)mtile + w_m * 64 + mf * 16 + g + half * 8;
            if (n >= N_OUT) continue;
            float inv = 1.f;
            if (w_n == 3) inv = 1.f / fmaxf(__ldg(g_imp + n), 1e-8f);
            #pragma unroll
            for (int nf = 0; nf < 4; nf++) {
                const int col = w_n * 32 + nf * 8 + 2 * tig;
                float2 r;
                r.x = fmaxf(fmaf(acc[mf][nf][half * 2 + 0], inv, bias[nf][0]), 0.f);
                r.y = fmaxf(fmaf(acc[mf][nf][half * 2 + 1], inv, bias[nf][1]), 0.f);
                *reinterpret_cast<float2*>(out + (size_t)n * CO + col) = r;
            }
        }
    }
}

// ---------------------------------------------------------------------------
extern "C" void kernel_launch(void* const* d_in, const int* in_sizes, int n_in,
                              void* d_out, int out_size) {
    const float* feats      = (const float*)d_in[0];
    const float* importance = (const float*)d_in[1];
    const float* W_a        = (const float*)d_in[2];
    const float* b_a        = (const float*)d_in[3];
    const float* W_b        = (const float*)d_in[4];
    const float* b_b        = (const float*)d_in[5];
    const int*   nbr        = (const int*)d_in[6];
    const int*   kid        = (const int*)d_in[7];
    const int*   oid        = (const int*)d_in[8];
    float*       out        = (float*)d_out;

    build_offsets_kernel<<<(NE + 255) / 256, 256>>>(oid);
    build_bp_kernel<<<(2 * NSTEPS * 4 * 32 * 8 + 255) / 256, 256>>>(W_a, W_b);
    bin_kernel<<<N_OUT / 8, 256>>>(feats, importance, nbr, kid, out);

    const int smem_bytes = 3 * SLOT;   // 98,304 B
    cudaFuncSetAttribute(gemm_kernel,
                         cudaFuncAttributeMaxDynamicSharedMemorySize, smem_bytes);
    gemm_kernel<<<NTILES, 256, smem_bytes>>>(b_a, b_b, out);
}